// round 5
// baseline (speedup 1.0000x reference)
#include <cuda_runtime.h>
#include <math.h>

// Problem shape (fixed for this dataset): B=32, A=3, S=80, NC=80
#define NCLS   80
#define CH     85          // 5 + NC
#define TCH    6
#define S2     6400        // S*S
#define NA     3
#define EPSF   1e-7f
#define BLOCKS 592         // 4 * 148 SMs, one wave
#define TPB    256
#define NWARPS (BLOCKS * (TPB / 32))

// per-block partials: [nool_sum, noobj_cnt, box_sum, objl_sum, cls_sum, obj_cnt]
__device__ double   g_part[BLOCKS * 6];
__device__ unsigned g_done = 0;

__device__ __forceinline__ float warp_sum(float v) {
    #pragma unroll
    for (int o = 16; o; o >>= 1) v += __shfl_xor_sync(0xffffffffu, v, o);
    return v;
}
__device__ __forceinline__ float warp_max(float v) {
    #pragma unroll
    for (int o = 16; o; o >>= 1) v = fmaxf(v, __shfl_xor_sync(0xffffffffu, v, o));
    return v;
}
__device__ __forceinline__ double warp_sum_d(double v) {
    #pragma unroll
    for (int o = 16; o; o >>= 1) v += __shfl_xor_sync(0xffffffffu, v, o);
    return v;
}

// Issue all loads for one obj cell. v0/v1/v2 are the warp-spread class logits
// (lane l holds classes l, l+32, l+64). p1..p4 / t1..t5 are uniform broadcast
// loads — L1 hits (same sectors as p0 / t0 / class rows already fetched).
__device__ __forceinline__ void obj_loads(
    const float* __restrict__ pred, const float* __restrict__ tgt,
    int cc, int lane,
    float& v0, float& v1, float& v2,
    float& p1, float& p2, float& p3, float& p4,
    float& t1, float& t2, float& t3, float& t4, float& t5)
{
    const int pb = cc * CH;
    const int tb = cc * TCH;
    v0 = __ldg(&pred[pb + 5  + lane]);
    v1 = __ldg(&pred[pb + 37 + lane]);
    v2 = (lane < 16) ? __ldg(&pred[pb + 69 + lane]) : 0.0f;
    p1 = __ldg(&pred[pb + 1]);
    p2 = __ldg(&pred[pb + 2]);
    p3 = __ldg(&pred[pb + 3]);
    p4 = __ldg(&pred[pb + 4]);
    t1 = __ldg(&tgt[tb + 1]);
    t2 = __ldg(&tgt[tb + 2]);
    t3 = __ldg(&tgt[tb + 3]);
    t4 = __ldg(&tgt[tb + 4]);
    t5 = __ldg(&tgt[tb + 5]);
}

// Process one 32-cell chunk at c0. t0/p0 already loaded (strided, per-lane).
__device__ __forceinline__ void process_chunk(
    int c0, int lane, float t0, float p0,
    const float* __restrict__ pred, const float* __restrict__ tgt,
    float a0w, float a0h, float a1w, float a1h, float a2w, float a2h,
    float& a_nool, float& a_ncnt, float& a_box, float& a_objl,
    float& a_cls, float& a_ocnt)
{
    // ---- no-object BCE-with-logits (t == 0 cells) ----
    if (t0 == 0.0f) {
        a_nool += fmaxf(p0, 0.f) + log1pf(expf(-fabsf(p0)));
        a_ncnt += 1.f;
    }

    // ---- obj cells (t == 1), warp-cooperative, 1-ahead prefetched ----
    unsigned bal = __ballot_sync(0xffffffffu, t0 == 1.0f);
    if (!bal) return;
    if (lane == 0) a_ocnt += (float)__popc(bal);

    int i = __ffs(bal) - 1;
    bal &= bal - 1;
    float v0, v1, v2, p1, p2, p3, p4, t1, t2, t3, t4, t5;
    obj_loads(pred, tgt, c0 + i, lane, v0, v1, v2, p1, p2, p3, p4, t1, t2, t3, t4, t5);

    while (true) {
        const int cur = c0 + i;
        const float w0 = v0, w1 = v1, w2 = v2;
        const float q1 = p1, q2 = p2, q3 = p3, q4 = p4;
        const float u1 = t1, u2 = t2, u3 = t3, u4 = t4, u5 = t5;
        const bool more = (bal != 0);
        if (more) {
            i = __ffs(bal) - 1;
            bal &= bal - 1;
            // prefetch next obj cell — overlaps the reduction chains below
            obj_loads(pred, tgt, c0 + i, lane,
                      v0, v1, v2, p1, p2, p3, p4, t1, t2, t3, t4, t5);
        }

        const float p0i = __shfl_sync(0xffffffffu, p0, cur - c0);
        const bool has2 = (lane < 16);

        // log-softmax pieces over 80 class logits
        float mx = fmaxf(fmaxf(w0, w1), has2 ? w2 : -INFINITY);
        mx = warp_max(mx);
        float e  = expf(w0 - mx) + expf(w1 - mx) + (has2 ? expf(w2 - mx) : 0.f);
        float sx = w0 + w1 + (has2 ? w2 : 0.f);
        e  = warp_sum(e);
        sx = warp_sum(sx);
        const float lse = mx + logf(e);

        // class logit for target class (uniform broadcast, L1 hit)
        const int k = (int)u5;
        const float xk = __ldg(&pred[cur * CH + 5 + k]);

        const float logpy   = xk - lse;
        const float sumlogp = sx - (float)NCLS * lse;
        const float ce = -(0.9f * logpy + (0.1f / (float)NCLS) * sumlogp);

        // object loss: BCE-with-logits applied to sigmoid(p0) with t=1 (quirk)
        const float sg = 1.f / (1.f + expf(-p0i));
        const float ol = fmaxf(sg, 0.f) - sg + log1pf(expf(-fabsf(sg)));

        // decoded box + CIoU
        const int aidx = (cur / S2) % NA;
        const float aw = (aidx == 0) ? a0w : ((aidx == 1) ? a1w : a2w);
        const float ah = (aidx == 0) ? a0h : ((aidx == 1) ? a1h : a2h);
        const float bx = 1.f / (1.f + expf(-q1));
        const float by = 1.f / (1.f + expf(-q2));
        const float bw = expf(q3) * aw;
        const float bh = expf(q4) * ah;

        const float x1a = bx - bw * 0.5f, x1b = bx + bw * 0.5f;
        const float y1a = by - bh * 0.5f, y1b = by + bh * 0.5f;
        const float x2a = u1 - u3 * 0.5f, x2b = u1 + u3 * 0.5f;
        const float y2a = u2 - u4 * 0.5f, y2b = u2 + u4 * 0.5f;
        const float iw = fmaxf(fminf(x1b, x2b) - fmaxf(x1a, x2a), 0.f);
        const float ih = fmaxf(fminf(y1b, y2b) - fmaxf(y1a, y2a), 0.f);
        const float inter = iw * ih;
        const float uni = bw * bh + u3 * u4 - inter + EPSF;
        const float iou = inter / uni;
        const float cw  = fmaxf(x1b, x2b) - fminf(x1a, x2a);
        const float chh = fmaxf(y1b, y2b) - fminf(y1a, y2a);
        const float c2  = cw * cw + chh * chh + EPSF;
        const float rho2 = (u1 - bx) * (u1 - bx) + (u2 - by) * (u2 - by);
        const float fo = 4.0f / ((float)M_PI * (float)M_PI);
        const float dv = atanf(u3 / (u4 + EPSF)) - atanf(bw / (bh + EPSF));
        const float v  = fo * dv * dv;
        const float alpha = v / (1.f - iou + v + EPSF);
        const float ciou  = iou - rho2 / c2 - alpha * v;

        if (lane == 0) {
            a_box  += (1.f - ciou);
            a_objl += ol;
            a_cls  += ce;
        }
        if (!more) break;
    }
}

__global__ __launch_bounds__(TPB, 4)
void yolo_loss_fused(const float* __restrict__ pred,
                     const float* __restrict__ tgt,
                     const float* __restrict__ anc,
                     float* __restrict__ out,
                     int cells)
{
    const int lane = threadIdx.x & 31;
    const int wg   = (blockIdx.x * blockDim.x + threadIdx.x) >> 5;

    // anchors to registers (broadcast loads)
    const float a0w = __ldg(&anc[0]), a0h = __ldg(&anc[1]);
    const float a1w = __ldg(&anc[2]), a1h = __ldg(&anc[3]);
    const float a2w = __ldg(&anc[4]), a2h = __ldg(&anc[5]);

    float a_nool = 0.f, a_ncnt = 0.f, a_box = 0.f, a_objl = 0.f,
          a_cls = 0.f, a_ocnt = 0.f;

    const int step = NWARPS * 32;
    // 4-deep pipelined grid-stride: at this shape every warp gets exactly 4
    // chunks in the first iteration (+1 remainder chunk for wg < 256)
    for (int c0 = wg * 32; c0 < cells; c0 += 4 * step) {
        const int cB = c0 + step, cC = c0 + 2 * step, cD = c0 + 3 * step;
        const bool hB = (cB < cells), hC = (cC < cells), hD = (cD < cells);

        const float tA = __ldg(&tgt[(c0 + lane) * TCH]);
        const float pA = __ldg(&pred[(c0 + lane) * CH]);
        float tB = -1.f, pB = 0.f, tC = -1.f, pC = 0.f, tD = -1.f, pD = 0.f;
        if (hB) { tB = __ldg(&tgt[(cB + lane) * TCH]); pB = __ldg(&pred[(cB + lane) * CH]); }
        if (hC) { tC = __ldg(&tgt[(cC + lane) * TCH]); pC = __ldg(&pred[(cC + lane) * CH]); }
        if (hD) { tD = __ldg(&tgt[(cD + lane) * TCH]); pD = __ldg(&pred[(cD + lane) * CH]); }

        process_chunk(c0, lane, tA, pA, pred, tgt, a0w, a0h, a1w, a1h, a2w, a2h,
                      a_nool, a_ncnt, a_box, a_objl, a_cls, a_ocnt);
        if (hB) process_chunk(cB, lane, tB, pB, pred, tgt, a0w, a0h, a1w, a1h, a2w, a2h,
                              a_nool, a_ncnt, a_box, a_objl, a_cls, a_ocnt);
        if (hC) process_chunk(cC, lane, tC, pC, pred, tgt, a0w, a0h, a1w, a1h, a2w, a2h,
                              a_nool, a_ncnt, a_box, a_objl, a_cls, a_ocnt);
        if (hD) process_chunk(cD, lane, tD, pD, pred, tgt, a0w, a0h, a1w, a1h, a2w, a2h,
                              a_nool, a_ncnt, a_box, a_objl, a_cls, a_ocnt);
    }

    // ---- block reduction to per-block double partial ----
    a_nool = warp_sum(a_nool);
    a_ncnt = warp_sum(a_ncnt);
    a_box  = warp_sum(a_box);
    a_objl = warp_sum(a_objl);
    a_cls  = warp_sum(a_cls);
    a_ocnt = warp_sum(a_ocnt);

    __shared__ float sh[8][6];
    const int wid = threadIdx.x >> 5;
    if (lane == 0) {
        sh[wid][0] = a_nool; sh[wid][1] = a_ncnt; sh[wid][2] = a_box;
        sh[wid][3] = a_objl; sh[wid][4] = a_cls;  sh[wid][5] = a_ocnt;
    }
    __syncthreads();

    __shared__ bool amlast;
    if (threadIdx.x == 0) {
        const int nw = blockDim.x >> 5;
        #pragma unroll
        for (int q = 0; q < 6; q++) {
            double d = 0.0;
            for (int w = 0; w < nw; w++) d += (double)sh[w][q];
            g_part[blockIdx.x * 6 + q] = d;
        }
        __threadfence();
        const unsigned old = atomicAdd(&g_done, 1u);
        amlast = (old == (unsigned)(gridDim.x - 1));
    }
    __syncthreads();

    // ---- last block performs the deterministic final reduction ----
    if (amlast) {
        __threadfence();
        double acc[6] = {0, 0, 0, 0, 0, 0};
        volatile double* gp = g_part;
        for (int i = threadIdx.x; i < BLOCKS; i += TPB) {
            #pragma unroll
            for (int q = 0; q < 6; q++) acc[q] += gp[i * 6 + q];
        }
        #pragma unroll
        for (int q = 0; q < 6; q++) acc[q] = warp_sum_d(acc[q]);

        __shared__ double fsh[8][6];
        if (lane == 0) {
            #pragma unroll
            for (int q = 0; q < 6; q++) fsh[wid][q] = acc[q];
        }
        __syncthreads();
        if (threadIdx.x == 0) {
            double tot[6] = {0, 0, 0, 0, 0, 0};
            #pragma unroll
            for (int w = 0; w < 8; w++)
                #pragma unroll
                for (int q = 0; q < 6; q++) tot[q] += fsh[w][q];
            const double nool = tot[0] / fmax(tot[1], 1.0);
            const double od   = fmax(tot[5], 1.0);
            out[0] = (float)(2.0 * (tot[2] / od) + tot[3] / od + nool + tot[4] / od);
            __threadfence();
            g_done = 0;  // reset for next graph replay
        }
    }
}

extern "C" void kernel_launch(void* const* d_in, const int* in_sizes, int n_in,
                              void* d_out, int out_size)
{
    (void)n_in; (void)out_size;
    const float* pred = (const float*)d_in[0];
    const float* tgt  = (const float*)d_in[1];
    const float* anc  = (const float*)d_in[2];
    float* out = (float*)d_out;

    const int cells = in_sizes[0] / CH;   // 614400
    yolo_loss_fused<<<BLOCKS, TPB>>>(pred, tgt, anc, out, cells);
}